// round 1
// baseline (speedup 1.0000x reference)
#include <cuda_runtime.h>
#include <math.h>

#define TT 128
#define BB 32
#define HH 256
#define II 256
#define G4 1024  // 4*H

// Scratch for the hoisted input projection: xproj[t][b][r] = emb@W_ih^T + b_ih + b_hh
__device__ float g_xproj[(size_t)TT * BB * G4];  // 16 MB

// ---------------------------------------------------------------------------
// Kernel A: xproj = emb @ W_ih^T + (b_ih + b_hh), M=4096, N=1024, K=256
// 64x64 tiles, 256 threads, 4x4 register blocking.
// ---------------------------------------------------------------------------
__global__ void __launch_bounds__(256) xproj_kernel(
    const float* __restrict__ emb, const float* __restrict__ W_ih,
    const float* __restrict__ b_ih, const float* __restrict__ b_hh)
{
    __shared__ float As[64][65];
    __shared__ float Bs[64][65];
    const int K = II;
    const int bm = blockIdx.x * 64, bn = blockIdx.y * 64;
    const int tx = threadIdx.x & 15, ty = threadIdx.x >> 4;
    float acc[4][4] = {};

    for (int k0 = 0; k0 < K; k0 += 64) {
        for (int i = threadIdx.x; i < 64 * 64; i += 256) {
            int r = i >> 6, cc = i & 63;
            As[r][cc] = emb[(size_t)(bm + r) * K + k0 + cc];
            Bs[r][cc] = W_ih[(size_t)(bn + r) * K + k0 + cc];
        }
        __syncthreads();
        #pragma unroll
        for (int k = 0; k < 64; k++) {
            float a[4], bv[4];
            #pragma unroll
            for (int i = 0; i < 4; i++) a[i] = As[ty * 4 + i][k];
            #pragma unroll
            for (int j = 0; j < 4; j++) bv[j] = Bs[tx * 4 + j][k];
            #pragma unroll
            for (int i = 0; i < 4; i++)
                #pragma unroll
                for (int j = 0; j < 4; j++)
                    acc[i][j] += a[i] * bv[j];
        }
        __syncthreads();
    }
    #pragma unroll
    for (int i = 0; i < 4; i++)
        #pragma unroll
        for (int j = 0; j < 4; j++) {
            int r = bm + ty * 4 + i, cI = bn + tx * 4 + j;
            g_xproj[(size_t)r * G4 + cI] = acc[i][j] + b_ih[cI] + b_hh[cI];
        }
}

// ---------------------------------------------------------------------------
// Kernel B: persistent recurrence. One CTA per batch element (32 CTAs,
// 1024 threads). h, c, and the full attention history buf[T][H] live in SMEM.
// W_hh / W_a are streamed from L2 every step (shared across all CTAs).
// ---------------------------------------------------------------------------
__global__ void __launch_bounds__(1024) recur_kernel(
    const int*   __restrict__ lens,
    const float* __restrict__ W_hh,   // [1024, 256]
    const float* __restrict__ W_a,    // [256, 512]
    const float* __restrict__ b_a,    // [256]
    float* __restrict__ out)          // output[T,B,H] ++ h_fin[B,H] ++ c_fin[B,H]
{
    extern __shared__ float sm[];
    float* buf   = sm;                  // T*H   = 32768 floats (128 KB)
    float* h_s   = buf  + TT * HH;      // 256
    float* c_s   = h_s  + HH;           // 256
    float* hu    = c_s  + HH;           // 256   (h used by gates: h_att or h)
    float* catx  = hu   + HH;           // 512   ([ctx, h_prev])
    float* sc    = catx + 2 * HH;       // 128   (scores -> alpha in place)
    float* part  = sc   + TT;           // 1024  (ctx partial sums)
    float* gates = part + 1024;         // 1024

    const int b    = blockIdx.x;
    const int tid  = threadIdx.x;
    const int warp = tid >> 5, lane = tid & 31;
    const int myLen = lens[b];

    if (tid < HH) { h_s[tid] = 0.f; c_s[tid] = 0.f; }
    __syncthreads();

    for (int t = 0; t < TT; t++) {
        if (t > 0) {
            // ---- scores[s] = dot(buf[s,:], h) for s < t : one warp per s ----
            for (int s = warp; s < t; s += 32) {
                const float* br = buf + s * HH;
                float p = 0.f;
                #pragma unroll
                for (int u = 0; u < HH / 32; u++)
                    p += br[lane + u * 32] * h_s[lane + u * 32];
                #pragma unroll
                for (int o = 16; o > 0; o >>= 1) p += __shfl_xor_sync(0xffffffffu, p, o);
                if (lane == 0) sc[s] = p;
            }
            __syncthreads();

            // ---- softmax over s < t (warp 0) ----
            if (warp == 0) {
                float m = -1e30f;
                for (int s = lane; s < t; s += 32) m = fmaxf(m, sc[s]);
                #pragma unroll
                for (int o = 16; o > 0; o >>= 1) m = fmaxf(m, __shfl_xor_sync(0xffffffffu, m, o));
                float sum = 0.f;
                for (int s = lane; s < t; s += 32) { float e = __expf(sc[s] - m); sc[s] = e; sum += e; }
                #pragma unroll
                for (int o = 16; o > 0; o >>= 1) sum += __shfl_xor_sync(0xffffffffu, sum, o);
                float inv = 1.f / sum;
                for (int s = lane; s < t; s += 32) sc[s] *= inv;
            }
            __syncthreads();

            // ---- ctx[j] = sum_s alpha[s] * buf[s][j] : 4-way split over s ----
            {
                int j  = tid & (HH - 1);
                int p4 = tid >> 8;  // 0..3
                float a = 0.f;
                for (int s = p4; s < t; s += 4) a += sc[s] * buf[s * HH + j];
                part[tid] = a;
            }
            __syncthreads();
            if (tid < HH) {
                catx[tid]      = part[tid] + part[tid + 256] + part[tid + 512] + part[tid + 768];
                catx[HH + tid] = h_s[tid];
            }
            __syncthreads();

            // ---- combine: hu = tanh(W_a @ [ctx, h] + b_a); warp -> 8 rows ----
            {
                int r0 = warp * 8;
                float a8[8] = {0.f, 0.f, 0.f, 0.f, 0.f, 0.f, 0.f, 0.f};
                #pragma unroll
                for (int m4 = 0; m4 < 4; m4++) {
                    int k = m4 * 128 + lane * 4;
                    float4 x = *(const float4*)&catx[k];
                    #pragma unroll
                    for (int r = 0; r < 8; r++) {
                        float4 w = *(const float4*)&W_a[(size_t)(r0 + r) * (2 * HH) + k];
                        a8[r] += w.x * x.x + w.y * x.y + w.z * x.z + w.w * x.w;
                    }
                }
                #pragma unroll
                for (int r = 0; r < 8; r++) {
                    float v = a8[r];
                    #pragma unroll
                    for (int o = 16; o > 0; o >>= 1) v += __shfl_xor_sync(0xffffffffu, v, o);
                    if (lane == r) hu[r0 + r] = tanhf(v + b_a[r0 + r]);
                }
            }
        } else {
            if (tid < HH) hu[tid] = h_s[tid];  // t = 0: no attention
        }
        __syncthreads();

        // ---- gates = xproj[t,b,:] + W_hh @ hu : warp -> 32 rows (4x8) ----
        const float* xp = g_xproj + ((size_t)t * BB + b) * G4;
        #pragma unroll
        for (int gr = 0; gr < 4; gr++) {
            int r0 = warp * 32 + gr * 8;
            float a8[8] = {0.f, 0.f, 0.f, 0.f, 0.f, 0.f, 0.f, 0.f};
            #pragma unroll
            for (int m4 = 0; m4 < 2; m4++) {
                int k = m4 * 128 + lane * 4;
                float4 x = *(const float4*)&hu[k];
                #pragma unroll
                for (int r = 0; r < 8; r++) {
                    float4 w = *(const float4*)&W_hh[(size_t)(r0 + r) * HH + k];
                    a8[r] += w.x * x.x + w.y * x.y + w.z * x.z + w.w * x.w;
                }
            }
            #pragma unroll
            for (int r = 0; r < 8; r++) {
                float v = a8[r];
                #pragma unroll
                for (int o = 16; o > 0; o >>= 1) v += __shfl_xor_sync(0xffffffffu, v, o);
                if (lane == r) gates[r0 + r] = v + xp[r0 + r];
            }
        }
        __syncthreads();

        // ---- LSTM cell update + outputs ----
        if (tid < HH) {
            int j = tid;
            float ig = gates[j], fg = gates[j + HH], gg = gates[j + 2 * HH], og = gates[j + 3 * HH];
            float si = 1.f / (1.f + __expf(-ig));
            float sf = 1.f / (1.f + __expf(-fg));
            float so = 1.f / (1.f + __expf(-og));
            float cn = sf * c_s[j] + si * tanhf(gg);
            float hn = so * tanhf(cn);
            c_s[j] = cn; h_s[j] = hn;
            buf[t * HH + j] = hn;
            out[((size_t)t * BB + b) * HH + j] = hn;
            if (t == myLen - 1) {
                out[(size_t)TT * BB * HH + (size_t)b * HH + j] = hn;                       // h_fin
                out[(size_t)TT * BB * HH + (size_t)BB * HH + (size_t)b * HH + j] = cn;     // c_fin
            }
        }
        __syncthreads();
    }
}

// ---------------------------------------------------------------------------
extern "C" void kernel_launch(void* const* d_in, const int* in_sizes, int n_in,
                              void* d_out, int out_size)
{
    const float* embs = (const float*)d_in[0];
    const int*   lens = (const int*)  d_in[1];
    const float* W_ih = (const float*)d_in[2];
    const float* W_hh = (const float*)d_in[3];
    const float* b_ih = (const float*)d_in[4];
    const float* b_hh = (const float*)d_in[5];
    const float* W_a  = (const float*)d_in[6];
    const float* b_a  = (const float*)d_in[7];
    float* out = (float*)d_out;

    const int smem_bytes = (TT * HH + 3 * HH + 2 * HH + TT + 1024 + 1024) * (int)sizeof(float);
    cudaFuncSetAttribute(recur_kernel, cudaFuncAttributeMaxDynamicSharedMemorySize, smem_bytes);

    xproj_kernel<<<dim3((TT * BB) / 64, G4 / 64), 256>>>(embs, W_ih, b_ih, b_hh);
    recur_kernel<<<BB, 1024, smem_bytes>>>(lens, W_hh, W_a, b_a, out);
}

// round 2
// speedup vs baseline: 2.0523x; 2.0523x over previous
#include <cuda_runtime.h>
#include <cstdint>
#include <math.h>

#define TT 128
#define BB 32
#define HH 256
#define II 256
#define G4 1024   // 4*H
#define CL 4      // cluster size (CTAs per batch element)
#define NTH 512   // threads per CTA

// Scratch for hoisted input projection: xproj[t][b][r] = emb@W_ih^T + b_ih + b_hh
__device__ float g_xproj[(size_t)TT * BB * G4];  // 16 MB

// ---------------------------------------------------------------------------
// Kernel A: xproj = emb @ W_ih^T + (b_ih + b_hh)   (M=4096, N=1024, K=256)
// ---------------------------------------------------------------------------
__global__ void __launch_bounds__(256) xproj_kernel(
    const float* __restrict__ emb, const float* __restrict__ W_ih,
    const float* __restrict__ b_ih, const float* __restrict__ b_hh)
{
    __shared__ float As[64][65];
    __shared__ float Bs[64][65];
    const int K = II;
    const int bm = blockIdx.x * 64, bn = blockIdx.y * 64;
    const int tx = threadIdx.x & 15, ty = threadIdx.x >> 4;
    float acc[4][4] = {};

    for (int k0 = 0; k0 < K; k0 += 64) {
        for (int i = threadIdx.x; i < 64 * 64; i += 256) {
            int r = i >> 6, cc = i & 63;
            As[r][cc] = emb[(size_t)(bm + r) * K + k0 + cc];
            Bs[r][cc] = W_ih[(size_t)(bn + r) * K + k0 + cc];
        }
        __syncthreads();
        #pragma unroll
        for (int k = 0; k < 64; k++) {
            float a[4], bv[4];
            #pragma unroll
            for (int i = 0; i < 4; i++) a[i] = As[ty * 4 + i][k];
            #pragma unroll
            for (int j = 0; j < 4; j++) bv[j] = Bs[tx * 4 + j][k];
            #pragma unroll
            for (int i = 0; i < 4; i++)
                #pragma unroll
                for (int j = 0; j < 4; j++)
                    acc[i][j] += a[i] * bv[j];
        }
        __syncthreads();
    }
    #pragma unroll
    for (int i = 0; i < 4; i++)
        #pragma unroll
        for (int j = 0; j < 4; j++) {
            int r = bm + ty * 4 + i, cI = bn + tx * 4 + j;
            g_xproj[(size_t)r * G4 + cI] = acc[i][j] + b_ih[cI] + b_hh[cI];
        }
}

// ---------------------------------------------------------------------------
// DSMEM / mbarrier helpers
// ---------------------------------------------------------------------------
__device__ __forceinline__ uint32_t smem_u32(const void* p) {
    return (uint32_t)__cvta_generic_to_shared(p);
}
__device__ __forceinline__ uint32_t my_rank() {
    uint32_t r;
    asm("mov.u32 %0, %%cluster_ctarank;" : "=r"(r));
    return r;
}
__device__ __forceinline__ void st_cluster(uint32_t laddr, int rank, float v) {
    uint32_t ra;
    asm volatile("mapa.shared::cluster.u32 %0, %1, %2;" : "=r"(ra) : "r"(laddr), "r"(rank));
    asm volatile("st.shared::cluster.f32 [%0], %1;" :: "r"(ra), "f"(v) : "memory");
}
__device__ __forceinline__ void bar_arrive_rank(uint32_t lbar, int rank) {
    uint32_t ra;
    asm volatile("mapa.shared::cluster.u32 %0, %1, %2;" : "=r"(ra) : "r"(lbar), "r"(rank));
    asm volatile("mbarrier.arrive.release.cluster.shared::cluster.b64 _, [%0];"
                 :: "r"(ra) : "memory");
}
__device__ __forceinline__ void bar_wait(uint32_t lbar, uint32_t parity) {
    asm volatile(
        "{\n\t.reg .pred P;\n\t"
        "LW_%=:\n\t"
        "mbarrier.try_wait.parity.acquire.cluster.shared::cta.b64 P, [%0], %1, 0x989680;\n\t"
        "@P bra LD_%=;\n\t"
        "bra LW_%=;\n\t"
        "LD_%=:\n\t}"
        :: "r"(lbar), "r"(parity) : "memory");
}

// ---------------------------------------------------------------------------
// Kernel B: cluster-of-4 recurrence. One 4-CTA cluster per batch element.
// CTA rank r owns: history slots s (s%4==r), hu rows [64r,64r+64),
// gate rows {g*256 + 64r + i} and the j-quarter [64r,64r+64) of the cell.
// ---------------------------------------------------------------------------
__global__ void __launch_bounds__(NTH, 1) __cluster_dims__(CL, 1, 1)
recur_kernel(
    const int*   __restrict__ lens,
    const float* __restrict__ W_hh,   // [1024, 256]
    const float* __restrict__ W_a,    // [256, 512]
    const float* __restrict__ b_a,    // [256]
    float* __restrict__ out)          // output[T,B,H] ++ h_fin[B,H] ++ c_fin[B,H]
{
    __shared__ float bufs[TT / CL][HH];   // my s-slice of history (32 KB)
    __shared__ float h[HH];               // full current h (replicated)
    __shared__ float hu[HH];              // full combined hidden (gathered)
    __shared__ float ctxp[CL][HH];        // ctx partials from each rank
    __shared__ float cat[2 * HH];         // [ctx, h]
    __shared__ float sc[TT];              // all scores (gathered)
    __shared__ float gates_s[HH];         // my quarter's 4 gate pre-acts (g*64+i)
    __shared__ float cS[HH / CL];         // my c quarter
    __shared__ float s_m, s_inv;
    __shared__ __align__(8) unsigned long long mbar[4];

    const int tid  = threadIdx.x;
    const int warp = tid >> 5, lane = tid & 31;
    const int r    = (int)my_rank();
    const int b    = blockIdx.x / CL;
    const int myLen = lens[b];

    const uint32_t bar_addr[4] = { smem_u32(&mbar[0]), smem_u32(&mbar[1]),
                                   smem_u32(&mbar[2]), smem_u32(&mbar[3]) };

    // init
    if (tid < HH) { h[tid] = 0.f; hu[tid] = 0.f; }
    if (tid < HH / CL) cS[tid] = 0.f;
    if (tid == 0) {
        #pragma unroll
        for (int k = 0; k < 4; k++)
            asm volatile("mbarrier.init.shared.b64 [%0], %1;" :: "r"(bar_addr[k]), "r"(CL) : "memory");
        asm volatile("fence.mbarrier_init.release.cluster;" ::: "memory");
    }
    __syncthreads();
    asm volatile("barrier.cluster.arrive.aligned;" ::: "memory");
    asm volatile("barrier.cluster.wait.aligned;" ::: "memory");

    for (int t = 0; t < TT; t++) {
        const uint32_t par = (uint32_t)(t & 1);

        // ---- Phase 1: scores for my s-slice, broadcast to all ranks ----
        if (t > 0) {
            for (int slot = warp; slot < TT / CL; slot += 16) {
                int s = slot * CL + r;
                if (s < t) {
                    float p = 0.f;
                    #pragma unroll
                    for (int u = 0; u < HH / 32; u++)
                        p += bufs[slot][lane + 32 * u] * h[lane + 32 * u];
                    #pragma unroll
                    for (int o = 16; o > 0; o >>= 1) p += __shfl_xor_sync(0xffffffffu, p, o);
                    if (lane < CL) st_cluster(smem_u32(&sc[s]), lane, p);
                }
            }
        }
        __syncthreads();
        if (tid < CL) bar_arrive_rank(bar_addr[0], tid);
        bar_wait(bar_addr[0], par);                               // B1

        // ---- Phase 2: softmax stats (redundant) + my ctx partial ----
        if (t > 0) {
            if (warp == 0) {
                float m = -1e30f;
                for (int s = lane; s < t; s += 32) m = fmaxf(m, sc[s]);
                #pragma unroll
                for (int o = 16; o > 0; o >>= 1) m = fmaxf(m, __shfl_xor_sync(0xffffffffu, m, o));
                float sum = 0.f;
                for (int s = lane; s < t; s += 32) sum += __expf(sc[s] - m);
                #pragma unroll
                for (int o = 16; o > 0; o >>= 1) sum += __shfl_xor_sync(0xffffffffu, sum, o);
                if (lane == 0) { s_m = m; s_inv = 1.f / sum; }
            }
            __syncthreads();
            if (tid < HH) {
                float m = s_m, inv = s_inv;
                float acc = 0.f;
                #pragma unroll 4
                for (int slot = 0; slot < TT / CL; slot++) {
                    int s = slot * CL + r;
                    if (s >= t) break;
                    acc += __expf(sc[s] - m) * inv * bufs[slot][tid];
                }
                uint32_t pa = smem_u32(&ctxp[r][tid]);
                #pragma unroll
                for (int peer = 0; peer < CL; peer++) st_cluster(pa, peer, acc);
            }
        }
        __syncthreads();
        if (tid < CL) bar_arrive_rank(bar_addr[1], tid);
        bar_wait(bar_addr[1], par);                               // B2

        // ---- Phase 3: cat = [ctx, h]; combine GEMV for my 64 hu rows ----
        if (t > 0) {
            if (tid < HH) {
                cat[tid]      = ctxp[0][tid] + ctxp[1][tid] + ctxp[2][tid] + ctxp[3][tid];
                cat[HH + tid] = h[tid];
            }
            __syncthreads();
            {
                float acc[4] = {0.f, 0.f, 0.f, 0.f};
                #pragma unroll
                for (int it = 0; it < 4; it++) {
                    float4 x = *(const float4*)&cat[it * 128 + lane * 4];
                    #pragma unroll
                    for (int rr = 0; rr < 4; rr++) {
                        int grow = 64 * r + warp * 4 + rr;
                        float4 w = __ldg((const float4*)&W_a[(size_t)grow * (2 * HH) + it * 128 + lane * 4]);
                        acc[rr] += w.x * x.x + w.y * x.y + w.z * x.z + w.w * x.w;
                    }
                }
                #pragma unroll
                for (int rr = 0; rr < 4; rr++) {
                    float v = acc[rr];
                    #pragma unroll
                    for (int o = 16; o > 0; o >>= 1) v += __shfl_xor_sync(0xffffffffu, v, o);
                    int grow = 64 * r + warp * 4 + rr;
                    if (lane < CL) {
                        float hv = tanhf(v + __ldg(&b_a[grow]));
                        st_cluster(smem_u32(&hu[grow]), lane, hv);
                    }
                }
            }
        }
        __syncthreads();
        if (tid < CL) bar_arrive_rank(bar_addr[2], tid);
        bar_wait(bar_addr[2], par);                               // B3

        // ---- Phase 4: gates for my 256 W_hh rows + cell update ----
        {
            const float* xp = g_xproj + ((size_t)t * BB + b) * G4;
            #pragma unroll
            for (int grp = 0; grp < 2; grp++) {
                float acc[8] = {0.f, 0.f, 0.f, 0.f, 0.f, 0.f, 0.f, 0.f};
                int lrbase = warp * 16 + grp * 8;
                #pragma unroll
                for (int it = 0; it < 2; it++) {
                    float4 x = *(const float4*)&hu[it * 128 + lane * 4];
                    #pragma unroll
                    for (int rr = 0; rr < 8; rr++) {
                        int lr = lrbase + rr;
                        int grow = (lr >> 6) * HH + 64 * r + (lr & 63);
                        float4 w = __ldcg((const float4*)&W_hh[(size_t)grow * HH + it * 128 + lane * 4]);
                        acc[rr] += w.x * x.x + w.y * x.y + w.z * x.z + w.w * x.w;
                    }
                }
                #pragma unroll
                for (int rr = 0; rr < 8; rr++) {
                    float v = acc[rr];
                    #pragma unroll
                    for (int o = 16; o > 0; o >>= 1) v += __shfl_xor_sync(0xffffffffu, v, o);
                    if (lane == rr) {
                        int lr = lrbase + rr;
                        int grow = (lr >> 6) * HH + 64 * r + (lr & 63);
                        gates_s[lr] = v + __ldg(&xp[grow]);
                    }
                }
            }
            __syncthreads();

            if (tid < HH / CL) {
                int j = 64 * r + tid;
                float ig = gates_s[tid],       fg = gates_s[64 + tid];
                float gg = gates_s[128 + tid], og = gates_s[192 + tid];
                float si = 1.f / (1.f + __expf(-ig));
                float sf = 1.f / (1.f + __expf(-fg));
                float so = 1.f / (1.f + __expf(-og));
                float cn = sf * cS[tid] + si * tanhf(gg);
                float hn = so * tanhf(cn);
                cS[tid] = cn;

                uint32_t ha = smem_u32(&h[j]);
                #pragma unroll
                for (int peer = 0; peer < CL; peer++) st_cluster(ha, peer, hn);
                // deposit into the owner rank's history slot for step t
                st_cluster(smem_u32(&bufs[t >> 2][j]), t & 3, hn);

                out[((size_t)t * BB + b) * HH + j] = hn;
                if (t == myLen - 1) {
                    out[(size_t)TT * BB * HH + (size_t)b * HH + j] = hn;
                    out[(size_t)TT * BB * HH + (size_t)BB * HH + (size_t)b * HH + j] = cn;
                }
            }
        }
        __syncthreads();
        if (tid < CL) bar_arrive_rank(bar_addr[3], tid);
        bar_wait(bar_addr[3], par);                               // B4
    }
}

// ---------------------------------------------------------------------------
extern "C" void kernel_launch(void* const* d_in, const int* in_sizes, int n_in,
                              void* d_out, int out_size)
{
    const float* embs = (const float*)d_in[0];
    const int*   lens = (const int*)  d_in[1];
    const float* W_ih = (const float*)d_in[2];
    const float* W_hh = (const float*)d_in[3];
    const float* b_ih = (const float*)d_in[4];
    const float* b_hh = (const float*)d_in[5];
    const float* W_a  = (const float*)d_in[6];
    const float* b_a  = (const float*)d_in[7];
    float* out = (float*)d_out;

    xproj_kernel<<<dim3((TT * BB) / 64, G4 / 64), 256>>>(embs, W_ih, b_ih, b_hh);
    recur_kernel<<<BB * CL, NTH>>>(lens, W_hh, W_a, b_a, out);
}